// round 8
// baseline (speedup 1.0000x reference)
#include <cuda_runtime.h>
#include <cuda_bf16.h>
#include <math.h>

// PolarVoxelizer R8: 2-kernel PDL graph, single-wave co-residency.
//   K1 k_zero  (primary, 296 blocks): float4 zero; triggers PDL at entry.
//   K2 k_voxel (secondary, ~367 blocks, 8 pts/thread): computes lin indices in
//      registers overlapped with K1, cudaGridDependencySynchronize(), scatters.
//   All voxel blocks resident in wave 1 -> no post-zero serialized tail.

#define Z_DEPTH   100
#define HALF_FOV  1.134f
#define R_MIN_C   2.7f
#define R_MAX_C   165.0f
#define SLOPE_REJ 2.2f        // atan(2.2)=1.1441 > HALF_FOV + any fp slop
#define MAX_RB    512
#define MAX_AB    256
#define PTS_PER_THREAD 8

// Exact searchsorted(side='left') given an approximate starting index.
__device__ __forceinline__ int lb_fixup(const float* __restrict__ a, int n, float v, int idx) {
    idx = min(max(idx, 0), n);
    while (idx > 0 && a[idx - 1] >= v) --idx;
    while (idx < n && a[idx] < v) ++idx;
    return idx;
}

__global__ __launch_bounds__(256) void k_zero(float4* __restrict__ out4, int n4)
{
#if __CUDA_ARCH__ >= 900
    cudaTriggerProgrammaticLaunchCompletion();   // let the voxel kernel co-schedule now
#endif
    int tid = blockIdx.x * blockDim.x + threadIdx.x;
    int stride = gridDim.x * blockDim.x;
    float4 z = make_float4(0.f, 0.f, 0.f, 0.f);
    for (int j = tid; j < n4; j += stride) out4[j] = z;
}

__global__ __launch_bounds__(256, 3) void k_voxel(
    const float4* __restrict__ lidars4,
    const float* __restrict__ r_bins,
    const float* __restrict__ angle_bins,
    float* __restrict__ out,
    int npts, int num_r, int num_a,
    unsigned long long div_magic,          // exact i/n_per_s via (i*magic)>>40
    float a0, float inv_astep,
    float log2_rmin, float inv_log2_1pd)
{
    __shared__ float s_r[MAX_RB];
    __shared__ float s_a[MAX_AB];
    for (int i = threadIdx.x; i < num_r; i += blockDim.x) s_r[i] = r_bins[i];
    for (int i = threadIdx.x; i < num_a; i += blockDim.x) s_a[i] = angle_bins[i];
    __syncthreads();

    int c = blockIdx.x * blockDim.x + threadIdx.x;   // chunk of 8 points
    int nchunks = (npts + PTS_PER_THREAD - 1) / PTS_PER_THREAD;

    int lins[PTS_PER_THREAD];
    #pragma unroll
    for (int k = 0; k < PTS_PER_THREAD; ++k) lins[k] = -1;

    if (c < nchunks) {
        int base = c * PTS_PER_THREAD;
        int v4 = c * (PTS_PER_THREAD * 3 / 4);     // 6 float4 per chunk
        float px[PTS_PER_THREAD], py[PTS_PER_THREAD], pz[PTS_PER_THREAD];

        #pragma unroll
        for (int g = 0; g < PTS_PER_THREAD / 4; ++g) {
            float4 q0 = lidars4[v4 + g * 3 + 0];
            float4 q1 = lidars4[v4 + g * 3 + 1];
            float4 q2 = lidars4[v4 + g * 3 + 2];
            px[g*4+0]=q0.x; py[g*4+0]=q0.y; pz[g*4+0]=q0.z;
            px[g*4+1]=q0.w; py[g*4+1]=q1.x; pz[g*4+1]=q1.y;
            px[g*4+2]=q1.z; py[g*4+2]=q1.w; pz[g*4+2]=q2.x;
            px[g*4+3]=q2.y; py[g*4+3]=q2.z; pz[g*4+3]=q2.w;
        }

        #pragma unroll
        for (int k = 0; k < PTS_PER_THREAD; ++k) {
            int i = base + k;
            float x = px[k], y = py[k], z = pz[k];

            // geometric pre-rejection: provably outside FOV (|angle| > 1.1441)
            if (i < npts && x > 0.0f && fabsf(y) <= SLOPE_REJ * x) {
                // radius: bit-exact vs XLA f32 (no FMA contraction, IEEE sqrt)
                float radius = __fsqrt_rn(__fadd_rn(__fmul_rn(x, x), __fmul_rn(y, y)));
                if ((radius < R_MAX_C) && (radius > R_MIN_C)) {
                    // angle: atan2f fast path, double refine near decision boundaries
                    float v = atan2f(y, x);
                    float eps = fmaxf(fabsf(v) * 1.0e-6f, 1.0e-7f);

                    int yg0 = (int)floorf((v - a0) * inv_astep);
                    int yg = lb_fixup(s_a, num_a, v, yg0);

                    bool near = (fabsf(fabsf(v) - HALF_FOV) <= eps);
                    if (yg < num_a && fabsf(v - s_a[yg])     <= eps) near = true;
                    if (yg > 0     && fabsf(v - s_a[yg - 1]) <= eps) near = true;
                    if (near) {
                        v = (float)atan2((double)y, (double)x);
                        yg = lb_fixup(s_a, num_a, v, yg);
                    }
                    if (fabsf(v) < HALF_FOV) {
                        int xg0 = (int)floorf((__log2f(radius) - log2_rmin) * inv_log2_1pd);
                        int xg = lb_fixup(s_r, num_r, radius, xg0);
                        int zg = (int)floorf(__fdiv_rn(__fsub_rn(z, -2.0f), 0.2f));
                        int s = (int)(((unsigned long long)i * div_magic) >> 40);
                        lins[k] = ((s * Z_DEPTH + zg) * num_a + yg) * num_r + xg;
                    }
                }
            }
        }
    }

#if __CUDA_ARCH__ >= 900
    cudaGridDependencySynchronize();   // wait for k_zero completion + visibility
#endif

    #pragma unroll
    for (int k = 0; k < PTS_PER_THREAD; ++k)
        if (lins[k] >= 0) out[lins[k]] = 1.0f;
}

extern "C" void kernel_launch(void* const* d_in, const int* in_sizes, int n_in,
                              void* d_out, int out_size) {
    const float* lidars     = (const float*)d_in[0];
    const float* r_bins     = (const float*)d_in[1];
    const float* angle_bins = (const float*)d_in[2];
    float* out = (float*)d_out;

    const int B = 2;  // output keeps only batch 0
    int num_r = in_sizes[1];
    int num_a = in_sizes[2];
    int npts  = in_sizes[0] / (3 * B);
    int S     = out_size / (Z_DEPTH * num_a * num_r);
    int n_per_s = npts / S;

    // Analytic grid params (guesses only; exactness via lb_fixup)
    double fov = 2.268;
    float a0 = (float)(-fov / 2.0);
    float inv_astep = (float)((num_a - 1) / fov);
    double delta = pow((165.0 + 0.0001) / 2.7, 1.0 / (double)(num_r - 1)) - 1.0;
    float log2_rmin = (float)(log(2.7) / log(2.0));
    float inv_log2_1pd = (float)(log(2.0) / log(1.0 + delta));

    // Exact floor(i / n_per_s) for i < 2^20: magic = ceil(2^40 / n_per_s)
    unsigned long long div_magic =
        ((1ULL << 40) + (unsigned long long)n_per_s - 1ULL) / (unsigned long long)n_per_s;

    int sms = 148;
    cudaDeviceGetAttribute(&sms, cudaDevAttrMultiProcessorCount, 0);

    // --- K1 (primary): zero output; small resident grid, triggers PDL early ---
    {
        int n4 = out_size / 4;
        int z_blocks = sms * 2;
        k_zero<<<z_blocks, 256>>>((float4*)out, n4);
    }

    // --- K2 (secondary, PDL): 8 pts/thread -> single co-resident wave ---
    {
        int nchunks = (npts + PTS_PER_THREAD - 1) / PTS_PER_THREAD;
        int v_blocks = (nchunks + 255) / 256;
        cudaLaunchConfig_t cfg = {};
        cfg.gridDim = dim3(v_blocks, 1, 1);
        cfg.blockDim = dim3(256, 1, 1);
        cfg.dynamicSmemBytes = 0;
        cfg.stream = 0;
        cudaLaunchAttribute attr[1];
        attr[0].id = cudaLaunchAttributeProgrammaticStreamSerialization;
        attr[0].val.programmaticStreamSerializationAllowed = 1;
        cfg.attrs = attr;
        cfg.numAttrs = 1;
        cudaLaunchKernelEx(&cfg, k_voxel,
            (const float4*)lidars, r_bins, angle_bins, out,
            npts, num_r, num_a, div_magic,
            a0, inv_astep, log2_rmin, inv_log2_1pd);
    }
}

// round 10
// speedup vs baseline: 1.2040x; 1.2040x over previous
#include <cuda_runtime.h>
#include <cuda_bf16.h>
#include <cstdint>
#include <math.h>

// PolarVoxelizer R10 (R9 + compile fix): TMA-based zeroing to free the LSU.
//   K1 k_zero_tma (primary): zero 32KB smem once, then cp.async.bulk
//     shared->global copies stream zeros at LTS cap with no LSU/issue cost.
//     Triggers PDL at entry.
//   K2 k_indices (secondary, PDL): per-point lin index -> g_lin scratch,
//     co-runs with K1 at full speed (disjoint memory, no LSU contention).
//   K3 k_scatter (normal launch): out[g_lin[i]] = 1.0f after both complete.

#define Z_DEPTH   100
#define HALF_FOV  1.134f
#define R_MIN_C   2.7f
#define R_MAX_C   165.0f
#define SLOPE_REJ 2.2f        // atan(2.2)=1.1441 > HALF_FOV + any fp slop
#define MAX_RB    512
#define MAX_AB    256
#define MAX_PTS   (1 << 20)
#define ZCHUNK    32768       // bytes per bulk copy (= smem buffer size)

__device__ int g_lin[MAX_PTS];   // per-point linear index or -1

// Exact searchsorted(side='left') given an approximate starting index.
__device__ __forceinline__ int lb_fixup(const float* __restrict__ a, int n, float v, int idx) {
    idx = min(max(idx, 0), n);
    while (idx > 0 && a[idx - 1] >= v) --idx;
    while (idx < n && a[idx] < v) ++idx;
    return idx;
}

__global__ __launch_bounds__(128) void k_zero_tma(char* __restrict__ out,
                                                  long long total_bytes)
{
#if __CUDA_ARCH__ >= 900
    cudaTriggerProgrammaticLaunchCompletion();   // let k_indices co-schedule now
#endif
    __shared__ __align__(128) float4 buf[ZCHUNK / 16];   // 32 KB of zeros

    for (int i = threadIdx.x; i < ZCHUNK / 16; i += blockDim.x)
        buf[i] = make_float4(0.f, 0.f, 0.f, 0.f);
    __syncthreads();
    asm volatile("fence.proxy.async.shared::cta;" ::: "memory");

    if (threadIdx.x == 0) {
        unsigned int saddr;
        asm("{ .reg .u64 t; cvta.to.shared.u64 t, %1; cvt.u32.u64 %0, t; }"
            : "=r"(saddr) : "l"(buf));

        long long nfull = total_bytes / ZCHUNK;
        for (long long c = blockIdx.x; c < nfull; c += gridDim.x) {
            char* g = out + c * (long long)ZCHUNK;
            asm volatile(
                "cp.async.bulk.global.shared::cta.bulk_group [%0], [%1], %2;"
                :: "l"(g), "r"(saddr), "r"((unsigned)ZCHUNK) : "memory");
        }
        // remainder (output bytes are 16B-aligned in practice; guard anyway)
        long long rem = total_bytes - nfull * ZCHUNK;
        if (blockIdx.x == 0 && rem >= 16) {
            char* g = out + nfull * (long long)ZCHUNK;
            asm volatile(
                "cp.async.bulk.global.shared::cta.bulk_group [%0], [%1], %2;"
                :: "l"(g), "r"(saddr), "r"((unsigned)(rem & ~15LL)) : "memory");
        }
        asm volatile("cp.async.bulk.commit_group;" ::: "memory");
        asm volatile("cp.async.bulk.wait_group 0;" ::: "memory");
    }
}

__global__ __launch_bounds__(256) void k_indices(
    const float4* __restrict__ lidars4,
    const float* __restrict__ r_bins,
    const float* __restrict__ angle_bins,
    int npts, int num_r, int num_a,
    unsigned long long div_magic,          // exact i/n_per_s via (i*magic)>>40
    float a0, float inv_astep,
    float log2_rmin, float inv_log2_1pd)
{
    __shared__ float s_r[MAX_RB];
    __shared__ float s_a[MAX_AB];
    for (int i = threadIdx.x; i < num_r; i += blockDim.x) s_r[i] = r_bins[i];
    for (int i = threadIdx.x; i < num_a; i += blockDim.x) s_a[i] = angle_bins[i];
    __syncthreads();

    int c = blockIdx.x * blockDim.x + threadIdx.x;   // chunk of 4 points
    int nchunks = (npts + 3) >> 2;
    if (c >= nchunks) return;

    int base = c * 4;
    int v4 = c * 3;
    float4 q0 = lidars4[v4 + 0];
    float4 q1 = lidars4[v4 + 1];
    float4 q2 = lidars4[v4 + 2];
    float px[4] = {q0.x, q0.w, q1.z, q2.y};
    float py[4] = {q0.y, q1.x, q1.w, q2.z};
    float pz[4] = {q0.z, q1.y, q2.x, q2.w};

    int lins[4];
    #pragma unroll
    for (int k = 0; k < 4; ++k) {
        int i = base + k;
        int lin = -1;
        float x = px[k], y = py[k], z = pz[k];

        // geometric pre-rejection: provably outside FOV (|angle| > 1.1441)
        if (i < npts && x > 0.0f && fabsf(y) <= SLOPE_REJ * x) {
            // radius: bit-exact vs XLA f32 (no FMA contraction, IEEE sqrt)
            float radius = __fsqrt_rn(__fadd_rn(__fmul_rn(x, x), __fmul_rn(y, y)));
            if ((radius < R_MAX_C) && (radius > R_MIN_C)) {
                // angle: atan2f fast path, double refine near decision boundaries
                float v = atan2f(y, x);
                float eps = fmaxf(fabsf(v) * 1.0e-6f, 1.0e-7f);

                int yg0 = (int)floorf((v - a0) * inv_astep);
                int yg = lb_fixup(s_a, num_a, v, yg0);

                bool near = (fabsf(fabsf(v) - HALF_FOV) <= eps);
                if (yg < num_a && fabsf(v - s_a[yg])     <= eps) near = true;
                if (yg > 0     && fabsf(v - s_a[yg - 1]) <= eps) near = true;
                if (near) {
                    v = (float)atan2((double)y, (double)x);
                    yg = lb_fixup(s_a, num_a, v, yg);
                }
                if (fabsf(v) < HALF_FOV) {
                    int xg0 = (int)floorf((__log2f(radius) - log2_rmin) * inv_log2_1pd);
                    int xg = lb_fixup(s_r, num_r, radius, xg0);
                    int zg = (int)floorf(__fdiv_rn(__fsub_rn(z, -2.0f), 0.2f));
                    int s = (int)(((unsigned long long)i * div_magic) >> 40);
                    lin = ((s * Z_DEPTH + zg) * num_a + yg) * num_r + xg;
                }
            }
        }
        lins[k] = lin;
    }

    // coalesced 16B store of 4 results (base = 4*c, always aligned)
    if (base + 3 < npts) {
        *(int4*)&g_lin[base] = make_int4(lins[0], lins[1], lins[2], lins[3]);
    } else {
        #pragma unroll
        for (int k = 0; k < 4; ++k)
            if (base + k < npts) g_lin[base + k] = lins[k];
    }
}

__global__ __launch_bounds__(256) void k_scatter(float* __restrict__ out, int npts)
{
    int i = blockIdx.x * blockDim.x + threadIdx.x;
    if (i >= npts) return;
    int lin = g_lin[i];
    if (lin >= 0) out[lin] = 1.0f;
}

extern "C" void kernel_launch(void* const* d_in, const int* in_sizes, int n_in,
                              void* d_out, int out_size) {
    const float* lidars     = (const float*)d_in[0];
    const float* r_bins     = (const float*)d_in[1];
    const float* angle_bins = (const float*)d_in[2];
    float* out = (float*)d_out;

    const int B = 2;  // output keeps only batch 0
    int num_r = in_sizes[1];
    int num_a = in_sizes[2];
    int npts  = in_sizes[0] / (3 * B);
    int S     = out_size / (Z_DEPTH * num_a * num_r);
    int n_per_s = npts / S;

    // Analytic grid params (guesses only; exactness via lb_fixup)
    double fov = 2.268;
    float a0 = (float)(-fov / 2.0);
    float inv_astep = (float)((num_a - 1) / fov);
    double delta = pow((165.0 + 0.0001) / 2.7, 1.0 / (double)(num_r - 1)) - 1.0;
    float log2_rmin = (float)(log(2.7) / log(2.0));
    float inv_log2_1pd = (float)(log(2.0) / log(1.0 + delta));

    // Exact floor(i / n_per_s) for i < 2^20: magic = ceil(2^40 / n_per_s)
    unsigned long long div_magic =
        ((1ULL << 40) + (unsigned long long)n_per_s - 1ULL) / (unsigned long long)n_per_s;

    int sms = 148;
    cudaDeviceGetAttribute(&sms, cudaDevAttrMultiProcessorCount, 0);

    // --- K1 (primary): TMA zero of the output; triggers PDL at entry ---
    k_zero_tma<<<sms, 128>>>((char*)out, (long long)out_size * 4);

    // --- K2 (secondary, PDL): index compute -> g_lin (disjoint from out) ---
    {
        int nchunks = (npts + 3) / 4;
        int v_blocks = (nchunks + 255) / 256;
        cudaLaunchConfig_t cfg = {};
        cfg.gridDim = dim3(v_blocks, 1, 1);
        cfg.blockDim = dim3(256, 1, 1);
        cfg.dynamicSmemBytes = 0;
        cfg.stream = 0;
        cudaLaunchAttribute attr[1];
        attr[0].id = cudaLaunchAttributeProgrammaticStreamSerialization;
        attr[0].val.programmaticStreamSerializationAllowed = 1;
        cfg.attrs = attr;
        cfg.numAttrs = 1;
        cudaLaunchKernelEx(&cfg, k_indices,
            (const float4*)lidars, r_bins, angle_bins,
            npts, num_r, num_a, div_magic,
            a0, inv_astep, log2_rmin, inv_log2_1pd);
    }

    // --- K3: scatter (normal launch: waits for BOTH K1 and K2) ---
    int k3_blocks = (npts + 255) / 256;
    k_scatter<<<k3_blocks, 256>>>(out, npts);
}

// round 11
// speedup vs baseline: 1.3397x; 1.1127x over previous
#include <cuda_runtime.h>
#include <cuda_bf16.h>
#include <cstdint>
#include <math.h>

// PolarVoxelizer R11: 2-kernel PDL graph, register-resident scatter.
//   K1 k_zero_tma (primary, 152x128): cp.async.bulk zeros (no LSU/issue cost),
//      triggers PDL at entry.
//   K2 k_voxel (secondary, 592x256, co-resident): each thread computes lin
//      indices for chunks {tid, tid+nthreads} into REGISTERS while K1 streams,
//      cudaGridDependencySynchronize(), then scatters 1.0f. No scratch, no K3.

#define Z_DEPTH   100
#define HALF_FOV  1.134f
#define R_MIN_C   2.7f
#define R_MAX_C   165.0f
#define SLOPE_REJ 2.2f        // atan(2.2)=1.1441 > HALF_FOV + any fp slop
#define MAX_RB    512
#define MAX_AB    256
#define ZCHUNK    32768       // bytes per bulk copy (= smem buffer size)
#define VOX_BLOCKS_PER_SM 4

// Exact searchsorted(side='left') given an approximate starting index.
__device__ __forceinline__ int lb_fixup(const float* __restrict__ a, int n, float v, int idx) {
    idx = min(max(idx, 0), n);
    while (idx > 0 && a[idx - 1] >= v) --idx;
    while (idx < n && a[idx] < v) ++idx;
    return idx;
}

__global__ __launch_bounds__(128) void k_zero_tma(char* __restrict__ out,
                                                  long long total_bytes)
{
#if __CUDA_ARCH__ >= 900
    cudaTriggerProgrammaticLaunchCompletion();   // let k_voxel co-schedule now
#endif
    __shared__ __align__(128) float4 buf[ZCHUNK / 16];   // 32 KB of zeros

    for (int i = threadIdx.x; i < ZCHUNK / 16; i += blockDim.x)
        buf[i] = make_float4(0.f, 0.f, 0.f, 0.f);
    __syncthreads();
    asm volatile("fence.proxy.async.shared::cta;" ::: "memory");

    if (threadIdx.x == 0) {
        unsigned int saddr;
        asm("{ .reg .u64 t; cvta.to.shared.u64 t, %1; cvt.u32.u64 %0, t; }"
            : "=r"(saddr) : "l"(buf));

        long long nfull = total_bytes / ZCHUNK;
        for (long long c = blockIdx.x; c < nfull; c += gridDim.x) {
            char* g = out + c * (long long)ZCHUNK;
            asm volatile(
                "cp.async.bulk.global.shared::cta.bulk_group [%0], [%1], %2;"
                :: "l"(g), "r"(saddr), "r"((unsigned)ZCHUNK) : "memory");
        }
        long long rem = total_bytes - nfull * ZCHUNK;
        if (blockIdx.x == 0 && rem >= 16) {
            char* g = out + nfull * (long long)ZCHUNK;
            asm volatile(
                "cp.async.bulk.global.shared::cta.bulk_group [%0], [%1], %2;"
                :: "l"(g), "r"(saddr), "r"((unsigned)(rem & ~15LL)) : "memory");
        }
        asm volatile("cp.async.bulk.commit_group;" ::: "memory");
        asm volatile("cp.async.bulk.wait_group 0;" ::: "memory");
    }
}

__global__ __launch_bounds__(256, VOX_BLOCKS_PER_SM) void k_voxel(
    const float4* __restrict__ lidars4,
    const float* __restrict__ r_bins,
    const float* __restrict__ angle_bins,
    float* __restrict__ out,
    int npts, int num_r, int num_a,
    unsigned long long div_magic,          // exact i/n_per_s via (i*magic)>>40
    float a0, float inv_astep,
    float log2_rmin, float inv_log2_1pd)
{
    __shared__ float s_r[MAX_RB];
    __shared__ float s_a[MAX_AB];
    for (int i = threadIdx.x; i < num_r; i += blockDim.x) s_r[i] = r_bins[i];
    for (int i = threadIdx.x; i < num_a; i += blockDim.x) s_a[i] = angle_bins[i];
    __syncthreads();

    const int tid = blockIdx.x * blockDim.x + threadIdx.x;
    const int nthreads = gridDim.x * blockDim.x;
    const int nchunks = (npts + 3) >> 2;

    int lins[2][4];
    #pragma unroll
    for (int j = 0; j < 2; ++j)
        #pragma unroll
        for (int k = 0; k < 4; ++k) lins[j][k] = -1;

    #pragma unroll
    for (int j = 0; j < 2; ++j) {
        int c = tid + j * nthreads;        // chunk of 4 points
        if (c >= nchunks) break;

        int base = c * 4;
        int v4 = c * 3;
        float4 q0 = lidars4[v4 + 0];
        float4 q1 = lidars4[v4 + 1];
        float4 q2 = lidars4[v4 + 2];
        float px[4] = {q0.x, q0.w, q1.z, q2.y};
        float py[4] = {q0.y, q1.x, q1.w, q2.z};
        float pz[4] = {q0.z, q1.y, q2.x, q2.w};

        #pragma unroll
        for (int k = 0; k < 4; ++k) {
            int i = base + k;
            float x = px[k], y = py[k], z = pz[k];

            // geometric pre-rejection: provably outside FOV (|angle| > 1.1441)
            if (i < npts && x > 0.0f && fabsf(y) <= SLOPE_REJ * x) {
                // radius: bit-exact vs XLA f32 (no FMA contraction, IEEE sqrt)
                float radius = __fsqrt_rn(__fadd_rn(__fmul_rn(x, x), __fmul_rn(y, y)));
                if ((radius < R_MAX_C) && (radius > R_MIN_C)) {
                    // angle: atan2f fast path, double refine near decision boundaries
                    float v = atan2f(y, x);
                    float eps = fmaxf(fabsf(v) * 1.0e-6f, 1.0e-7f);

                    int yg0 = (int)floorf((v - a0) * inv_astep);
                    int yg = lb_fixup(s_a, num_a, v, yg0);

                    bool near = (fabsf(fabsf(v) - HALF_FOV) <= eps);
                    if (yg < num_a && fabsf(v - s_a[yg])     <= eps) near = true;
                    if (yg > 0     && fabsf(v - s_a[yg - 1]) <= eps) near = true;
                    if (near) {
                        v = (float)atan2((double)y, (double)x);
                        yg = lb_fixup(s_a, num_a, v, yg);
                    }
                    if (fabsf(v) < HALF_FOV) {
                        int xg0 = (int)floorf((__log2f(radius) - log2_rmin) * inv_log2_1pd);
                        int xg = lb_fixup(s_r, num_r, radius, xg0);
                        int zg = (int)floorf(__fdiv_rn(__fsub_rn(z, -2.0f), 0.2f));
                        int s = (int)(((unsigned long long)i * div_magic) >> 40);
                        lins[j][k] = ((s * Z_DEPTH + zg) * num_a + yg) * num_r + xg;
                    }
                }
            }
        }
    }

#if __CUDA_ARCH__ >= 900
    cudaGridDependencySynchronize();   // wait for k_zero_tma completion + visibility
#endif

    #pragma unroll
    for (int j = 0; j < 2; ++j)
        #pragma unroll
        for (int k = 0; k < 4; ++k)
            if (lins[j][k] >= 0) out[lins[j][k]] = 1.0f;
}

extern "C" void kernel_launch(void* const* d_in, const int* in_sizes, int n_in,
                              void* d_out, int out_size) {
    const float* lidars     = (const float*)d_in[0];
    const float* r_bins     = (const float*)d_in[1];
    const float* angle_bins = (const float*)d_in[2];
    float* out = (float*)d_out;

    const int B = 2;  // output keeps only batch 0
    int num_r = in_sizes[1];
    int num_a = in_sizes[2];
    int npts  = in_sizes[0] / (3 * B);
    int S     = out_size / (Z_DEPTH * num_a * num_r);
    int n_per_s = npts / S;

    // Analytic grid params (guesses only; exactness via lb_fixup)
    double fov = 2.268;
    float a0 = (float)(-fov / 2.0);
    float inv_astep = (float)((num_a - 1) / fov);
    double delta = pow((165.0 + 0.0001) / 2.7, 1.0 / (double)(num_r - 1)) - 1.0;
    float log2_rmin = (float)(log(2.7) / log(2.0));
    float inv_log2_1pd = (float)(log(2.0) / log(1.0 + delta));

    // Exact floor(i / n_per_s) for i < 2^20: magic = ceil(2^40 / n_per_s)
    unsigned long long div_magic =
        ((1ULL << 40) + (unsigned long long)n_per_s - 1ULL) / (unsigned long long)n_per_s;

    int sms = 148;
    cudaDeviceGetAttribute(&sms, cudaDevAttrMultiProcessorCount, 0);

    // --- K1 (primary): TMA zero of the output; triggers PDL at entry ---
    k_zero_tma<<<sms, 128>>>((char*)out, (long long)out_size * 4);

    // --- K2 (secondary, PDL): co-resident voxel grid, <=2 chunks/thread ---
    {
        int nchunks = (npts + 3) / 4;
        int v_blocks = sms * VOX_BLOCKS_PER_SM;
        // ensure 2 chunks/thread covers all chunks
        int need = (nchunks + 2 * 256 - 1) / (2 * 256);
        if (v_blocks < need) v_blocks = need;

        cudaLaunchConfig_t cfg = {};
        cfg.gridDim = dim3(v_blocks, 1, 1);
        cfg.blockDim = dim3(256, 1, 1);
        cfg.dynamicSmemBytes = 0;
        cfg.stream = 0;
        cudaLaunchAttribute attr[1];
        attr[0].id = cudaLaunchAttributeProgrammaticStreamSerialization;
        attr[0].val.programmaticStreamSerializationAllowed = 1;
        cfg.attrs = attr;
        cfg.numAttrs = 1;
        cudaLaunchKernelEx(&cfg, k_voxel,
            (const float4*)lidars, r_bins, angle_bins, out,
            npts, num_r, num_a, div_magic,
            a0, inv_astep, log2_rmin, inv_log2_1pd);
    }
}

// round 12
// speedup vs baseline: 1.4668x; 1.0949x over previous
#include <cuda_runtime.h>
#include <cuda_bf16.h>
#include <cstdint>
#include <math.h>

// PolarVoxelizer R12: R11 + occupancy push on the voxel kernel.
//   K1 k_zero_tma (primary, 148x128): cp.async.bulk zeros (no LSU/issue cost),
//      triggers PDL at entry.
//   K2 k_voxel (secondary, 733x256, launch_bounds(256,5), 1 chunk/thread):
//      computes 4 lin indices into REGISTERS while K1 streams,
//      cudaGridDependencySynchronize(), then scatters 1.0f.
//   Co-residency: 5 voxel (48 regs) + 1 zero block per SM, single wave.

#define Z_DEPTH   100
#define HALF_FOV  1.134f
#define R_MIN_C   2.7f
#define R_MAX_C   165.0f
#define SLOPE_REJ 2.2f        // atan(2.2)=1.1441 > HALF_FOV + any fp slop
#define MAX_RB    512
#define MAX_AB    256
#define ZCHUNK    32768       // bytes per bulk copy (= smem buffer size)

// Exact searchsorted(side='left') given an approximate starting index.
__device__ __forceinline__ int lb_fixup(const float* __restrict__ a, int n, float v, int idx) {
    idx = min(max(idx, 0), n);
    while (idx > 0 && a[idx - 1] >= v) --idx;
    while (idx < n && a[idx] < v) ++idx;
    return idx;
}

__global__ __launch_bounds__(128) void k_zero_tma(char* __restrict__ out,
                                                  long long total_bytes)
{
#if __CUDA_ARCH__ >= 900
    cudaTriggerProgrammaticLaunchCompletion();   // let k_voxel co-schedule now
#endif
    __shared__ __align__(128) float4 buf[ZCHUNK / 16];   // 32 KB of zeros

    for (int i = threadIdx.x; i < ZCHUNK / 16; i += blockDim.x)
        buf[i] = make_float4(0.f, 0.f, 0.f, 0.f);
    __syncthreads();
    asm volatile("fence.proxy.async.shared::cta;" ::: "memory");

    if (threadIdx.x == 0) {
        unsigned int saddr;
        asm("{ .reg .u64 t; cvta.to.shared.u64 t, %1; cvt.u32.u64 %0, t; }"
            : "=r"(saddr) : "l"(buf));

        long long nfull = total_bytes / ZCHUNK;
        for (long long c = blockIdx.x; c < nfull; c += gridDim.x) {
            char* g = out + c * (long long)ZCHUNK;
            asm volatile(
                "cp.async.bulk.global.shared::cta.bulk_group [%0], [%1], %2;"
                :: "l"(g), "r"(saddr), "r"((unsigned)ZCHUNK) : "memory");
        }
        long long rem = total_bytes - nfull * ZCHUNK;
        if (blockIdx.x == 0 && rem >= 16) {
            char* g = out + nfull * (long long)ZCHUNK;
            asm volatile(
                "cp.async.bulk.global.shared::cta.bulk_group [%0], [%1], %2;"
                :: "l"(g), "r"(saddr), "r"((unsigned)(rem & ~15LL)) : "memory");
        }
        asm volatile("cp.async.bulk.commit_group;" ::: "memory");
        asm volatile("cp.async.bulk.wait_group 0;" ::: "memory");
    }
}

__global__ __launch_bounds__(256, 5) void k_voxel(
    const float4* __restrict__ lidars4,
    const float* __restrict__ r_bins,
    const float* __restrict__ angle_bins,
    float* __restrict__ out,
    int npts, int num_r, int num_a,
    unsigned long long div_magic,          // exact i/n_per_s via (i*magic)>>40
    float a0, float inv_astep,
    float log2_rmin, float inv_log2_1pd)
{
    __shared__ float s_r[MAX_RB];
    __shared__ float s_a[MAX_AB];
    for (int i = threadIdx.x; i < num_r; i += blockDim.x) s_r[i] = r_bins[i];
    for (int i = threadIdx.x; i < num_a; i += blockDim.x) s_a[i] = angle_bins[i];
    __syncthreads();

    const int c = blockIdx.x * blockDim.x + threadIdx.x;   // chunk of 4 points
    const int nchunks = (npts + 3) >> 2;

    int lins[4] = {-1, -1, -1, -1};

    if (c < nchunks) {
        int base = c * 4;
        int v4 = c * 3;
        float4 q0 = lidars4[v4 + 0];
        float4 q1 = lidars4[v4 + 1];
        float4 q2 = lidars4[v4 + 2];
        float px[4] = {q0.x, q0.w, q1.z, q2.y};
        float py[4] = {q0.y, q1.x, q1.w, q2.z};
        float pz[4] = {q0.z, q1.y, q2.x, q2.w};

        #pragma unroll
        for (int k = 0; k < 4; ++k) {
            int i = base + k;
            float x = px[k], y = py[k], z = pz[k];

            // geometric pre-rejection: provably outside FOV (|angle| > 1.1441)
            if (i < npts && x > 0.0f && fabsf(y) <= SLOPE_REJ * x) {
                // radius: bit-exact vs XLA f32 (no FMA contraction, IEEE sqrt)
                float radius = __fsqrt_rn(__fadd_rn(__fmul_rn(x, x), __fmul_rn(y, y)));
                if ((radius < R_MAX_C) && (radius > R_MIN_C)) {
                    // angle: atan2f fast path, double refine near decision boundaries
                    float v = atan2f(y, x);
                    float eps = fmaxf(fabsf(v) * 1.0e-6f, 1.0e-7f);

                    int yg0 = (int)floorf((v - a0) * inv_astep);
                    int yg = lb_fixup(s_a, num_a, v, yg0);

                    bool near = (fabsf(fabsf(v) - HALF_FOV) <= eps);
                    if (yg < num_a && fabsf(v - s_a[yg])     <= eps) near = true;
                    if (yg > 0     && fabsf(v - s_a[yg - 1]) <= eps) near = true;
                    if (near) {
                        v = (float)atan2((double)y, (double)x);
                        yg = lb_fixup(s_a, num_a, v, yg);
                    }
                    if (fabsf(v) < HALF_FOV) {
                        int xg0 = (int)floorf((__log2f(radius) - log2_rmin) * inv_log2_1pd);
                        int xg = lb_fixup(s_r, num_r, radius, xg0);
                        int zg = (int)floorf(__fdiv_rn(__fsub_rn(z, -2.0f), 0.2f));
                        int s = (int)(((unsigned long long)i * div_magic) >> 40);
                        lins[k] = ((s * Z_DEPTH + zg) * num_a + yg) * num_r + xg;
                    }
                }
            }
        }
    }

#if __CUDA_ARCH__ >= 900
    cudaGridDependencySynchronize();   // wait for k_zero_tma completion + visibility
#endif

    #pragma unroll
    for (int k = 0; k < 4; ++k)
        if (lins[k] >= 0) out[lins[k]] = 1.0f;
}

extern "C" void kernel_launch(void* const* d_in, const int* in_sizes, int n_in,
                              void* d_out, int out_size) {
    const float* lidars     = (const float*)d_in[0];
    const float* r_bins     = (const float*)d_in[1];
    const float* angle_bins = (const float*)d_in[2];
    float* out = (float*)d_out;

    const int B = 2;  // output keeps only batch 0
    int num_r = in_sizes[1];
    int num_a = in_sizes[2];
    int npts  = in_sizes[0] / (3 * B);
    int S     = out_size / (Z_DEPTH * num_a * num_r);
    int n_per_s = npts / S;

    // Analytic grid params (guesses only; exactness via lb_fixup)
    double fov = 2.268;
    float a0 = (float)(-fov / 2.0);
    float inv_astep = (float)((num_a - 1) / fov);
    double delta = pow((165.0 + 0.0001) / 2.7, 1.0 / (double)(num_r - 1)) - 1.0;
    float log2_rmin = (float)(log(2.7) / log(2.0));
    float inv_log2_1pd = (float)(log(2.0) / log(1.0 + delta));

    // Exact floor(i / n_per_s) for i < 2^20: magic = ceil(2^40 / n_per_s)
    unsigned long long div_magic =
        ((1ULL << 40) + (unsigned long long)n_per_s - 1ULL) / (unsigned long long)n_per_s;

    int sms = 148;
    cudaDeviceGetAttribute(&sms, cudaDevAttrMultiProcessorCount, 0);

    // --- K1 (primary): TMA zero of the output; triggers PDL at entry ---
    k_zero_tma<<<sms, 128>>>((char*)out, (long long)out_size * 4);

    // --- K2 (secondary, PDL): 1 chunk/thread, 5 blocks/SM, single wave ---
    {
        int nchunks = (npts + 3) / 4;
        int v_blocks = (nchunks + 255) / 256;
        cudaLaunchConfig_t cfg = {};
        cfg.gridDim = dim3(v_blocks, 1, 1);
        cfg.blockDim = dim3(256, 1, 1);
        cfg.dynamicSmemBytes = 0;
        cfg.stream = 0;
        cudaLaunchAttribute attr[1];
        attr[0].id = cudaLaunchAttributeProgrammaticStreamSerialization;
        attr[0].val.programmaticStreamSerializationAllowed = 1;
        cfg.attrs = attr;
        cfg.numAttrs = 1;
        cudaLaunchKernelEx(&cfg, k_voxel,
            (const float4*)lidars, r_bins, angle_bins, out,
            npts, num_r, num_a, div_magic,
            a0, inv_astep, log2_rmin, inv_log2_1pd);
    }
}